// round 10
// baseline (speedup 1.0000x reference)
#include <cuda_runtime.h>
#include <math.h>

// AttFusion: out[g,c,s] = sum_m softmax_m(<x0,xm>_c / 16) * x[m,c,s]
// x: [28, 256, 8448] fp32; out: [8, 256, 8448] fp32.
//
// R10: pipelined persistent tiles. Each CTA runs 4 tiles (32 positions each)
// with n-sequence (5,2,4,3) — class 0 = groups {3,0,2,1}, class 1 =
// {7,5,6,4} — so all 528 CTAs have identical work (one balanced wave).
// The fused loop overlaps pass-2 of tile t (L2 reads + stores) with pass-1
// DRAM reads of tile t+1, keeping HBM streaming continuously. Double-
// buffered smem partials; one barrier per tile. float2 lanes (16 pos-duos x
// 2 channel rows per warp) keep registers < 64 for 4 CTAs/SM.

#define C_DIM   256
#define S_DIM   8448
#define N_MAX   5
#define NWARPS  8
#define NT      4
#define FULL    0xffffffffu

// per-class schedules, n-sequence (5,2,4,3) for both classes
__device__ __constant__ int d_off[2][NT] = {{9, 0, 5, 2}, {23, 17, 19, 14}};
__device__ __constant__ int d_g[2][NT]   = {{3, 0, 2, 1}, {7,  5,  6,  4}};

// fused loop: pass-2 of current tile (NC agents, L2-hot) + pass-1 of next
// tile (NN agents, DRAM). NC==0 -> prologue (pass-1 only); NN==0 -> last tile.
template <int NC, int NN>
__device__ __forceinline__ void fused_tile(
    const float* curb, const float* nextb, float* outb,
    const float2* wv, float2* pn, size_t mstr)
{
#pragma unroll
    for (int m = 0; m < NN; m++) pn[m] = make_float2(0.f, 0.f);

    const float* cp = curb;
    const float* np = nextb;
    float*       op = outb;
#pragma unroll 2
    for (int kk = 0; kk < 16; kk++) {
        float2 xn[NN > 0 ? NN : 1];
#pragma unroll
        for (int m = 0; m < NN; m++)
            xn[m] = *reinterpret_cast<const float2*>(np + m * mstr);
        float2 xc[NC > 0 ? NC : 1];
#pragma unroll
        for (int m = 0; m < NC; m++)
            xc[m] = __ldlu(reinterpret_cast<const float2*>(cp + m * mstr));
#pragma unroll
        for (int m = 0; m < NN; m++) {
            pn[m].x += xn[0].x * xn[m].x;
            pn[m].y += xn[0].y * xn[m].y;
        }
        if (NC > 0) {
            float2 acc = make_float2(0.f, 0.f);
#pragma unroll
            for (int m = 0; m < NC; m++) {
                acc.x += wv[m].x * xc[m].x;
                acc.y += wv[m].y * xc[m].y;
            }
            __stwt(reinterpret_cast<float2*>(op), acc);
        }
        cp += 2 * S_DIM; np += 2 * S_DIM; op += 2 * S_DIM;
    }
}

// combine the 2 channel rows in the warp, lanes 0..15 publish duo partials
template <int NN>
__device__ __forceinline__ void store_partials(
    float2* pn, float (*red)[NWARPS][32], int warp, int lo4, int rowg)
{
#pragma unroll
    for (int m = 0; m < NN; m++) {
        pn[m].x += __shfl_down_sync(FULL, pn[m].x, 16);
        pn[m].y += __shfl_down_sync(FULL, pn[m].y, 16);
    }
    if (rowg == 0) {
#pragma unroll
        for (int m = 0; m < NN; m++)
            *reinterpret_cast<float2*>(&red[m][warp][2 * lo4]) = pn[m];
    }
}

// per-warp redundant softmax (lane = position), distribute to duo lanes
template <int NC>
__device__ __forceinline__ void softmax_wv(
    const float (*red)[NWARPS][32], int lane, int lo4, float2* wv)
{
    float d[N_MAX];
#pragma unroll
    for (int m = 0; m < N_MAX; m++) {
        if (m < NC) {
            float a = 0.0f;
#pragma unroll
            for (int w = 0; w < NWARPS; w++) a += red[m][w][lane];
            d[m] = a * 0.0625f;                  // 1/sqrt(256)
        } else {
            d[m] = -1e30f;
        }
    }
    float mx = d[0];
#pragma unroll
    for (int m = 1; m < N_MAX; m++) mx = fmaxf(mx, d[m]);
    float wl[N_MAX], s = 0.0f;
#pragma unroll
    for (int m = 0; m < NC; m++) { wl[m] = __expf(d[m] - mx); s += wl[m]; }
    const float inv = 1.0f / s;
#pragma unroll
    for (int m = 0; m < NC; m++) {
        const float v = wl[m] * inv;
        wv[m].x = __shfl_sync(FULL, v, 2 * lo4);
        wv[m].y = __shfl_sync(FULL, v, 2 * lo4 + 1);
    }
}

__global__ __launch_bounds__(256, 4)
void attfusion_kernel(const float* __restrict__ x, float* __restrict__ out) {
    __shared__ float red[2][N_MAX][NWARPS][32];   // double-buffered partials

    const int cls  = blockIdx.y;
    const int j    = blockIdx.x;
    const int tid  = threadIdx.x;
    const int lane = tid & 31;
    const int warp = tid >> 5;
    const int lo4  = lane & 15;                   // position duo 2*lo4, +1
    const int rowg = lane >> 4;                   // channel sub-row 0..1
    const int c0   = warp * 32;

    const size_t mstr   = (size_t)C_DIM * S_DIM;
    const size_t lpos   = (size_t)(c0 + rowg) * S_DIM + j * 32 + lo4 * 2;

    int offs[NT], gs[NT];
#pragma unroll
    for (int t = 0; t < NT; t++) { offs[t] = d_off[cls][t]; gs[t] = d_g[cls][t]; }

    const float* b0 = x + (size_t)offs[0] * mstr + lpos;
    const float* b1 = x + (size_t)offs[1] * mstr + lpos;
    const float* b2 = x + (size_t)offs[2] * mstr + lpos;
    const float* b3 = x + (size_t)offs[3] * mstr + lpos;
    float* o0 = out + (size_t)gs[0] * mstr + lpos;
    float* o1 = out + (size_t)gs[1] * mstr + lpos;
    float* o2 = out + (size_t)gs[2] * mstr + lpos;
    float* o3 = out + (size_t)gs[3] * mstr + lpos;

    float2 wv[N_MAX], pn[N_MAX];

    // prologue: pass-1 of tile 0 (n=5)
    fused_tile<0, 5>(b0, b0, o0, wv, pn, mstr);
    store_partials<5>(pn, red[0], warp, lo4, rowg);
    __syncthreads();
    softmax_wv<5>(red[0], lane, lo4, wv);

    // tile 0 (n=5) out + tile 1 (n=2) in
    fused_tile<5, 2>(b0, b1, o0, wv, pn, mstr);
    store_partials<2>(pn, red[1], warp, lo4, rowg);
    __syncthreads();
    softmax_wv<2>(red[1], lane, lo4, wv);

    // tile 1 (n=2) out + tile 2 (n=4) in
    fused_tile<2, 4>(b1, b2, o1, wv, pn, mstr);
    store_partials<4>(pn, red[0], warp, lo4, rowg);
    __syncthreads();
    softmax_wv<4>(red[0], lane, lo4, wv);

    // tile 2 (n=4) out + tile 3 (n=3) in
    fused_tile<4, 3>(b2, b3, o2, wv, pn, mstr);
    store_partials<3>(pn, red[1], warp, lo4, rowg);
    __syncthreads();
    softmax_wv<3>(red[1], lane, lo4, wv);

    // tile 3 (n=3) out, no next
    fused_tile<3, 0>(b3, b3, o3, wv, pn, mstr);
}

extern "C" void kernel_launch(void* const* d_in, const int* in_sizes, int n_in,
                              void* d_out, int out_size) {
    const float* x = (const float*)d_in[0];
    float* out = (float*)d_out;

    dim3 grid(S_DIM / 32, 2);                    // 264 x 2 = 528 CTAs, 1 wave
    attfusion_kernel<<<grid, 256>>>(x, out);
}

// round 11
// speedup vs baseline: 1.1550x; 1.1550x over previous
#include <cuda_runtime.h>
#include <math.h>

// AttFusion: out[g,c,s] = sum_m softmax_m(<x0,xm>_c / 16) * x[m,c,s]
// x: [28, 256, 8448] fp32; out: [8, 256, 8448] fp32.
//
// R11: 2-tile pipelined CTAs, compile-time n. CTA = (group g, 64 positions
// = two 32-pos tiles t0,t1). Flow: P1(t0) -> softmax -> fused middle
// (per chunk: t1 DRAM loads interleaved with t0 __ldlu L2 reads + __stwt
// stores) -> softmax -> P2(t1). DRAM-read issue covers ~3/4 of CTA lifetime.
// Warp = 4 channel rows x 8 pos-quads: 4 full 128B lines per LDG.128.
// grid 132x8 = 1056 CTAs @ 3/SM = 2.4 waves (straggler smoothing).

#define C_DIM   256
#define S_DIM   8448
#define N_MAX   5
#define NWARPS  8
#define FULL    0xffffffffu

__device__ __constant__ int c_off[8] = {0, 2, 5, 9, 14, 17, 19, 23};
__device__ __constant__ int c_len[8] = {2, 3, 4, 5, 3, 2, 4, 5};

template <int N>
__device__ __forceinline__ void reduce_store(
    float4* p, float (*red)[NWARPS][32], int warp, int lo3, int rowg)
{
#pragma unroll
    for (int m = 0; m < N; m++) {
        p[m].x += __shfl_down_sync(FULL, p[m].x, 16);
        p[m].y += __shfl_down_sync(FULL, p[m].y, 16);
        p[m].z += __shfl_down_sync(FULL, p[m].z, 16);
        p[m].w += __shfl_down_sync(FULL, p[m].w, 16);
        p[m].x += __shfl_down_sync(FULL, p[m].x, 8);
        p[m].y += __shfl_down_sync(FULL, p[m].y, 8);
        p[m].z += __shfl_down_sync(FULL, p[m].z, 8);
        p[m].w += __shfl_down_sync(FULL, p[m].w, 8);
    }
    if (rowg == 0) {
#pragma unroll
        for (int m = 0; m < N; m++)
            *reinterpret_cast<float4*>(&red[m][warp][lo3 * 4]) = p[m];
    }
}

// per-warp redundant softmax: lane = position, then broadcast to quad lanes
template <int N>
__device__ __forceinline__ void softmax_wv(
    const float (*red)[NWARPS][32], int lane, int lo3, float4* wv)
{
    float d[N];
#pragma unroll
    for (int m = 0; m < N; m++) {
        float a = 0.0f;
#pragma unroll
        for (int w = 0; w < NWARPS; w++) a += red[m][w][lane];
        d[m] = a * 0.0625f;                    // 1/sqrt(256)
    }
    float mx = d[0];
#pragma unroll
    for (int m = 1; m < N; m++) mx = fmaxf(mx, d[m]);
    float wl[N], s = 0.0f;
#pragma unroll
    for (int m = 0; m < N; m++) { wl[m] = __expf(d[m] - mx); s += wl[m]; }
    const float inv = 1.0f / s;
#pragma unroll
    for (int m = 0; m < N; m++) {
        const float v = wl[m] * inv;
        wv[m].x = __shfl_sync(FULL, v, 4 * lo3 + 0);
        wv[m].y = __shfl_sync(FULL, v, 4 * lo3 + 1);
        wv[m].z = __shfl_sync(FULL, v, 4 * lo3 + 2);
        wv[m].w = __shfl_sync(FULL, v, 4 * lo3 + 3);
    }
}

template <int N>
__device__ __forceinline__ void run_group(
    const float* __restrict__ xg, float* __restrict__ og,
    float (*red0)[NWARPS][32], float (*red1)[NWARPS][32],
    int s0, int lane, int warp, int lo3, int rowg)
{
    const size_t mstr = (size_t)C_DIM * S_DIM;
    const size_t lpos = (size_t)(warp * 32 + rowg) * S_DIM + s0 + lo3 * 4;
    const float* xb0 = xg + lpos;
    const float* xb1 = xb0 + 32;
    float* ob0 = og + lpos;
    float* ob1 = ob0 + 32;

    // ---- P1(t0): partial dots, 8 channel chunks ----
    float4 p[N];
#pragma unroll
    for (int m = 0; m < N; m++) p[m] = make_float4(0.f, 0.f, 0.f, 0.f);
    {
        const float* ptr = xb0;
#pragma unroll
        for (int kk = 0; kk < 8; kk++) {
            float4 xv[N];
#pragma unroll
            for (int m = 0; m < N; m++)
                xv[m] = *reinterpret_cast<const float4*>(ptr + m * mstr);
#pragma unroll
            for (int m = 0; m < N; m++) {
                p[m].x += xv[0].x * xv[m].x;
                p[m].y += xv[0].y * xv[m].y;
                p[m].z += xv[0].z * xv[m].z;
                p[m].w += xv[0].w * xv[m].w;
            }
            ptr += 4 * S_DIM;
        }
    }
    reduce_store<N>(p, red0, warp, lo3, rowg);
    __syncthreads();

    // prefetch t1 chunk 0 (independent of softmax)
    float4 xn[N];
#pragma unroll
    for (int m = 0; m < N; m++)
        xn[m] = *reinterpret_cast<const float4*>(xb1 + m * mstr);

    float4 wv[N];
    softmax_wv<N>(red0, lane, lo3, wv);

    // ---- middle: P2(t0) from L2 interleaved with P1(t1) from DRAM ----
    float4 pn[N];
#pragma unroll
    for (int m = 0; m < N; m++) pn[m] = make_float4(0.f, 0.f, 0.f, 0.f);
    {
        const float* cp = xb0;
        const float* np = xb1;
        float*       op = ob0;
#pragma unroll
        for (int kk = 0; kk < 8; kk++) {
#pragma unroll
            for (int m = 0; m < N; m++) {
                pn[m].x += xn[0].x * xn[m].x;
                pn[m].y += xn[0].y * xn[m].y;
                pn[m].z += xn[0].z * xn[m].z;
                pn[m].w += xn[0].w * xn[m].w;
            }
            float4 xc[N];
#pragma unroll
            for (int m = 0; m < N; m++)
                xc[m] = __ldlu(reinterpret_cast<const float4*>(cp + m * mstr));
            float4 acc = make_float4(0.f, 0.f, 0.f, 0.f);
#pragma unroll
            for (int m = 0; m < N; m++) {
                acc.x += wv[m].x * xc[m].x;
                acc.y += wv[m].y * xc[m].y;
                acc.z += wv[m].z * xc[m].z;
                acc.w += wv[m].w * xc[m].w;
            }
            __stwt(reinterpret_cast<float4*>(op), acc);
            if (kk < 7) {
                np += 4 * S_DIM;
#pragma unroll
                for (int m = 0; m < N; m++)
                    xn[m] = *reinterpret_cast<const float4*>(np + m * mstr);
            }
            cp += 4 * S_DIM;
            op += 4 * S_DIM;
        }
    }
    reduce_store<N>(pn, red1, warp, lo3, rowg);
    __syncthreads();
    softmax_wv<N>(red1, lane, lo3, wv);

    // ---- P2(t1): weighted sum from L2 ----
    {
        const float* ptr = xb1;
        float* op = ob1;
#pragma unroll
        for (int kk = 0; kk < 8; kk++) {
            float4 xc[N];
#pragma unroll
            for (int m = 0; m < N; m++)
                xc[m] = __ldlu(reinterpret_cast<const float4*>(ptr + m * mstr));
            float4 acc = make_float4(0.f, 0.f, 0.f, 0.f);
#pragma unroll
            for (int m = 0; m < N; m++) {
                acc.x += wv[m].x * xc[m].x;
                acc.y += wv[m].y * xc[m].y;
                acc.z += wv[m].z * xc[m].z;
                acc.w += wv[m].w * xc[m].w;
            }
            __stwt(reinterpret_cast<float4*>(op), acc);
            ptr += 4 * S_DIM;
            op  += 4 * S_DIM;
        }
    }
}

__global__ __launch_bounds__(256, 3)
void attfusion_kernel(const float* __restrict__ x, float* __restrict__ out) {
    __shared__ float red0[N_MAX][NWARPS][32];   // 5 KB
    __shared__ float red1[N_MAX][NWARPS][32];   // 5 KB

    const int g    = blockIdx.y;
    const int s0   = blockIdx.x * 64;            // two 32-pos tiles
    const int tid  = threadIdx.x;
    const int lane = tid & 31;
    const int warp = tid >> 5;
    const int lo3  = lane & 7;                   // position quad
    const int rowg = lane >> 3;                  // channel sub-row 0..3

    const size_t mstr = (size_t)C_DIM * S_DIM;
    const float* xg = x + (size_t)c_off[g] * mstr;
    float*       og = out + (size_t)g * mstr;

    switch (c_len[g]) {
        case 2: run_group<2>(xg, og, red0, red1, s0, lane, warp, lo3, rowg); break;
        case 3: run_group<3>(xg, og, red0, red1, s0, lane, warp, lo3, rowg); break;
        case 4: run_group<4>(xg, og, red0, red1, s0, lane, warp, lo3, rowg); break;
        default: run_group<5>(xg, og, red0, red1, s0, lane, warp, lo3, rowg); break;
    }
}

extern "C" void kernel_launch(void* const* d_in, const int* in_sizes, int n_in,
                              void* d_out, int out_size) {
    const float* x = (const float*)d_in[0];
    float* out = (float*)d_out;

    dim3 grid(S_DIM / 64, 8);                    // 132 x 8 = 1056 CTAs
    attfusion_kernel<<<grid, 256>>>(x, out);
}